// round 11
// baseline (speedup 1.0000x reference)
#include <cuda_runtime.h>
#include <cuda.h>
#include <cuda_fp16.h>
#include <cstdint>

#define BSZ   1024
#define LSEQ  200
#define CCH   80
#define OOUT  30
#define ROWS_TOT (BSZ * LSEQ)      // 204800
#define NCOL  240
#define KDIM  300
#define KSTR  320                  // zero-padded K for fp16 W in gmem
#define XKP   304                  // zero-padded K for fp16 X in gmem
#define BN    120                  // N per CTA (2 CTAs cover 240)
#define NCHUNK 5                   // K chunks of 64h (last: 3 of 4 k16 steps)
#define NCTA  1626
#define NTHR  192                  // 6 warps: 2M x 3N, warp tile 64x40
#define ASTG  16384                // A stage: 128 rows x 64h (128B rows, SW128)
#define B_OFF (2 * ASTG)           // 32768
#define BSTRIDE 624                // B row stride bytes (312 halves)
#define B_BYTES (BN * BSTRIDE)     // 74880
#define SMEM_DYN (B_OFF + B_BYTES + 1024)   // 108672 -> 2 CTAs/SM
#define DSS   121

__device__ int    g_h[2][BSZ * CCH];
__device__ __half g_wh[2][NCOL * KSTR];
__device__ __half g_xh[2][ROWS_TOT * XKP];

// ---------------- PTX helpers ----------------
__device__ __forceinline__ uint32_t smem_u32(const void* p) {
    uint32_t a;
    asm("{ .reg .u64 t; cvta.to.shared.u64 t, %1; cvt.u32.u64 %0, t; }" : "=r"(a) : "l"(p));
    return a;
}
#define MBAR_INIT(a, c) asm volatile("mbarrier.init.shared.b64 [%0], %1;" :: "r"(a), "r"(c) : "memory")
#define MBAR_EXPECT(a, b) asm volatile("mbarrier.arrive.expect_tx.shared.b64 _, [%0], %1;" :: "r"(a), "r"(b) : "memory")
#define MBAR_WAIT(a, ph) do { \
    uint32_t _m = (a), _p = (ph), _d; \
    asm volatile("{\n\t.reg .pred p;\n\t" \
        "mbarrier.try_wait.parity.acquire.cta.shared::cta.b64 p, [%1], %2;\n\t" \
        "selp.b32 %0, 1, 0, p;\n\t}" : "=r"(_d) : "r"(_m), "r"(_p) : "memory"); \
    if (!_d) { \
        asm volatile("{\n\t.reg .pred P1;\n\tWL_%=:\n\t" \
            "mbarrier.try_wait.parity.acquire.cta.shared::cta.b64 P1, [%0], %1, 0x989680;\n\t" \
            "@P1 bra.uni WD_%=;\n\tbra.uni WL_%=;\n\tWD_%=:\n\t}" \
            :: "r"(_m), "r"(_p) : "memory"); \
    } } while (0)

__device__ __forceinline__ void tma2d(uint32_t dst, const CUtensorMap* m, int x, int y, uint32_t mb) {
    asm volatile("cp.async.bulk.tensor.2d.shared::cta.global.tile.mbarrier::complete_tx::bytes "
                 "[%0], [%1, {%2, %3}], [%4];" :: "r"(dst), "l"(m), "r"(x), "r"(y), "r"(mb) : "memory");
}
__device__ __forceinline__ void cpa16(uint32_t dst, const void* src) {
    asm volatile("cp.async.cg.shared.global [%0], [%1], 16;" :: "r"(dst), "l"(src) : "memory");
}
#define CP_COMMIT() asm volatile("cp.async.commit_group;" ::: "memory")
#define CP_WAIT0()  asm volatile("cp.async.wait_group 0;" ::: "memory")

__device__ __forceinline__ uint32_t packh2(float lo, float hi) {
    uint32_t r;
    asm("cvt.rn.f16x2.f32 %0, %1, %2;" : "=r"(r) : "f"(hi), "f"(lo));
    return r;
}
__device__ __forceinline__ void ldsm4(uint32_t* r, uint32_t addr) {
    asm volatile("ldmatrix.sync.aligned.m8n8.x4.shared.b16 {%0,%1,%2,%3}, [%4];"
                 : "=r"(r[0]), "=r"(r[1]), "=r"(r[2]), "=r"(r[3]) : "r"(addr));
}
__device__ __forceinline__ void ldsm2(uint32_t* r, uint32_t addr) {
    asm volatile("ldmatrix.sync.aligned.m8n8.x2.shared.b16 {%0,%1}, [%2];"
                 : "=r"(r[0]), "=r"(r[1]) : "r"(addr));
}
__device__ __forceinline__ void mma16h(uint32_t* c, const uint32_t* a, uint32_t b0, uint32_t b1) {
    asm volatile("mma.sync.aligned.m16n8k16.row.col.f16.f16.f16.f16 "
                 "{%0,%1}, {%2,%3,%4,%5}, {%6,%7}, {%0,%1};"
                 : "+r"(c[0]), "+r"(c[1])
                 : "r"(a[0]), "r"(a[1]), "r"(a[2]), "r"(a[3]), "r"(b0), "r"(b1));
}

// ---------------- kernels ----------------
__global__ void nop_kernel() {}

__global__ void prep_kernel(const float* __restrict__ w1, const float* __restrict__ w2) {
    const int i = blockIdx.x * blockDim.x + threadIdx.x;   // 163840
    ((int*)g_h)[i] = 0;
    if (i < NCOL * KSTR) {
        const int row = i / KSTR, col = i % KSTR;
        g_wh[0][i] = __float2half_rn((col < KDIM) ? w1[row * KDIM + col] : 0.f);
        g_wh[1][i] = __float2half_rn((col < KDIM) ? w2[row * KDIM + col] : 0.f);
    }
}

// X fp32 -> fp16 gmem; one thread = one 8-half unit (38 units/row)
__global__ void __launch_bounds__(1024) xconv_kernel(
    const float* __restrict__ x1, const float* __restrict__ x2)
{
    const int g = blockIdx.x * 1024 + threadIdx.x;
    const int sub = blockIdx.y;
    const int row = g / 38, u = g - row * 38;
    const int k = u * 8;
    const float* src = (sub ? x2 : x1) + (long)row * KDIM + k;
    const float4 a = *(const float4*)src;
    float4 b = make_float4(0.f, 0.f, 0.f, 0.f);
    if (u < 37) b = *(const float4*)(src + 4);
    uint4 o;
    o.x = packh2(a.x, a.y); o.y = packh2(a.z, a.w);
    o.z = packh2(b.x, b.y); o.w = packh2(b.z, b.w);
    *(uint4*)(g_xh[sub] + (long)row * XKP + k) = o;
}

__global__ void __launch_bounds__(NTHR, 2) gemm_conv_kernel(
    const __grid_constant__ CUtensorMap xm1, const __grid_constant__ CUtensorMap xm2,
    const float* __restrict__ b1, const float* __restrict__ b2)
{
    extern __shared__ char dynsm[];
    __shared__ __align__(8) unsigned long long mb_full[2];

    const int tid = threadIdx.x, wid = tid >> 5, lane = tid & 31;
    const int warp_m = wid / 3, warp_n = wid % 3;    // 2M x 3N, warp tile 64x40
    const int nsplit = blockIdx.x & 1;
    const int sub = blockIdx.x >> 1;
    const int nbase = nsplit * BN;
    const float* bc = sub ? b2 : b1;
    const CUtensorMap* xm = sub ? &xm2 : &xm1;
    const __half* Wh = g_wh[sub];
    const int r0 = blockIdx.y * 126;

    const uint32_t raw = smem_u32(dynsm);
    const uint32_t sb = (raw + 1023u) & ~1023u;
    char* dptr = dynsm + (sb - raw);
    const uint32_t Bb = sb + B_OFF;

    if (tid == 0) {
        MBAR_INIT(smem_u32(&mb_full[0]), 1);
        MBAR_INIT(smem_u32(&mb_full[1]), 1);
        asm volatile("fence.proxy.async.shared::cta;" ::: "memory");
        MBAR_EXPECT(smem_u32(&mb_full[0]), ASTG);
        tma2d(sb,        xm, 0,  r0, smem_u32(&mb_full[0]));
        MBAR_EXPECT(smem_u32(&mb_full[1]), ASTG);
        tma2d(sb + ASTG, xm, 64, r0, smem_u32(&mb_full[1]));
    }

    // ---- B resident load (once): 120 rows x 39 16B-units = 4680 ----
    #pragma unroll
    for (int it = 0; it < 25; it++) {
        const int idx = tid + it * NTHR;
        if (idx < BN * 39) {
            const int row = idx / 39, u = idx % 39;
            cpa16(Bb + row * BSTRIDE + u * 16, Wh + (nbase + row) * KSTR + u * 8);
        }
    }
    CP_COMMIT();
    CP_WAIT0();
    __syncthreads();

    uint32_t acc[4][5][2];
    #pragma unroll
    for (int mt = 0; mt < 4; mt++)
        #pragma unroll
        for (int nt = 0; nt < 5; nt++) { acc[mt][nt][0] = 0u; acc[mt][nt][1] = 0u; }

    // fragment lane addressing
    const int l15 = lane & 15, lhi = lane >> 4;
    const int arow0 = warp_m * 64 + l15;             // mt adds 16
    const int bmat = lane >> 3;
    const int brow_off4 = ((bmat & 2) << 2) + (lane & 7);
    const int bk_off4 = (bmat & 1) << 3;
    const int brow_off2 = lane & 7;
    const int bk_off2 = (bmat & 1) << 3;

    for (int c = 0; c < NCHUNK; c++) {
        const int s = c & 1;
        MBAR_WAIT(smem_u32(&mb_full[s]), (c >> 1) & 1);
        const uint32_t Ab = sb + s * ASTG;
        const int ksmax = (c == NCHUNK - 1) ? 3 : 4; // K=304 real
        #pragma unroll
        for (int ks = 0; ks < 4; ks++) {
            if (ks >= ksmax) break;
            uint32_t a[4][4];
            #pragma unroll
            for (int mt = 0; mt < 4; mt++) {
                const int arow = arow0 + mt * 16;
                ldsm4(a[mt], Ab + arow * 128 + ((ks * 32 + lhi * 16) ^ ((arow & 7) << 4)));
            }
            const uint32_t kbyte = c * 128 + ks * 32;
            #pragma unroll
            for (int pair = 0; pair < 2; pair++) {
                const int brow = warp_n * 40 + pair * 16 + brow_off4;
                uint32_t b[4];
                ldsm4(b, Bb + brow * BSTRIDE + kbyte + bk_off4 * 2);
                #pragma unroll
                for (int mt = 0; mt < 4; mt++) {
                    mma16h(acc[mt][2 * pair],     a[mt], b[0], b[1]);
                    mma16h(acc[mt][2 * pair + 1], a[mt], b[2], b[3]);
                }
            }
            {
                const int brow = warp_n * 40 + 32 + brow_off2;
                uint32_t b[2];
                ldsm2(b, Bb + brow * BSTRIDE + kbyte + bk_off2 * 2);
                #pragma unroll
                for (int mt = 0; mt < 4; mt++)
                    mma16h(acc[mt][4], a[mt], b[0], b[1]);
            }
        }
        __syncthreads();
        if (tid == 0 && c + 2 < NCHUNK) {
            MBAR_EXPECT(smem_u32(&mb_full[s]), ASTG);
            tma2d(sb + s * ASTG, xm, (c + 2) * 64, r0, smem_u32(&mb_full[s]));
        }
    }

    // ---- stage D (128 x 120) into smem ----
    const int grp = lane >> 2, tig = lane & 3;
    float* ds = (float*)dptr;
    #pragma unroll
    for (int mt = 0; mt < 4; mt++)
        #pragma unroll
        for (int nt = 0; nt < 5; nt++) {
            const int rb = warp_m * 64 + mt * 16 + grp;
            const int n0 = warp_n * 40 + nt * 8 + tig * 2;
            const float2 lo = __half22float2(*(__half2*)&acc[mt][nt][0]);
            const float2 hi = __half22float2(*(__half2*)&acc[mt][nt][1]);
            ds[rb * DSS + n0]           = lo.x;
            ds[rb * DSS + n0 + 1]       = lo.y;
            ds[(rb + 8) * DSS + n0]     = hi.x;
            ds[(rb + 8) * DSS + n0 + 1] = hi.y;
        }
    __syncthreads();

    // ---- 3-tap diagonal combine + bias + relu + segment max + atomicMax ----
    const int bA = r0 / LSEQ;
    const int chbase = nsplit * 40;
    for (int cl = wid; cl < 40; cl += 6) {
        const int ch = chbase + cl;
        const float bias = __ldg(&bc[ch]);
        float mA = 0.f, mB = 0.f;
        #pragma unroll
        for (int k = 0; k < 4; k++) {
            const int i = lane + 32 * k;
            if (i >= 126) continue;
            const int g = r0 + i;
            if (g + 2 >= ROWS_TOT) continue;
            if ((g % LSEQ) > (LSEQ - 3)) continue;
            float v = ds[i * DSS + 3 * cl] + ds[(i + 1) * DSS + 3 * cl + 1]
                    + ds[(i + 2) * DSS + 3 * cl + 2] + bias;
            v = fmaxf(v, 0.f);
            if (g / LSEQ == bA) mA = fmaxf(mA, v); else mB = fmaxf(mB, v);
        }
        #pragma unroll
        for (int off = 16; off; off >>= 1) {
            mA = fmaxf(mA, __shfl_xor_sync(0xffffffffu, mA, off));
            mB = fmaxf(mB, __shfl_xor_sync(0xffffffffu, mB, off));
        }
        if (lane == 0) {
            if (mA > 0.f) atomicMax(&g_h[sub][bA * CCH + ch], __float_as_int(mA));
            if (mB > 0.f && bA + 1 < BSZ)
                atomicMax(&g_h[sub][(bA + 1) * CCH + ch], __float_as_int(mB));
        }
    }
}

__global__ void __launch_bounds__(256) finish_kernel(
    const float* __restrict__ wfc1, const float* __restrict__ bfc1,
    const float* __restrict__ wfc2, const float* __restrict__ bfc2,
    float* __restrict__ out)
{
    const int wid = threadIdx.x >> 5, j = threadIdx.x & 31;
    const int b = blockIdx.x * 8 + wid;
    float p = 0.f;
    if (j < OOUT) {
        float s1 = bfc1[j], s2 = bfc2[j];
        const int* h1 = &g_h[0][b * CCH];
        const int* h2 = &g_h[1][b * CCH];
        #pragma unroll 8
        for (int c = 0; c < CCH; c++) {
            s1 += __int_as_float(h1[c]) * wfc1[j * CCH + c];
            s2 += __int_as_float(h2[c]) * wfc2[j * CCH + c];
        }
        p = fmaxf(s1, 0.f) * fmaxf(s2, 0.f);
    }
    #pragma unroll
    for (int off = 16; off; off >>= 1) p += __shfl_xor_sync(0xffffffffu, p, off);
    if (j == 0) out[b] = p;
}

// ---------------- host ----------------
typedef CUresult (*EncodeFn)(CUtensorMap*, CUtensorMapDataType, cuuint32_t, void*,
                             const cuuint64_t*, const cuuint64_t*, const cuuint32_t*, const cuuint32_t*,
                             CUtensorMapInterleave, CUtensorMapSwizzle, CUtensorMapL2promotion,
                             CUtensorMapFloatOOBfill);

static void encXH(EncodeFn f, CUtensorMap* m, void* p) {
    cuuint64_t gd[2] = {XKP, ROWS_TOT};
    cuuint64_t gs[1] = {XKP * 2};
    cuuint32_t bx[2] = {64, 128};
    cuuint32_t es[2] = {1, 1};
    f(m, CU_TENSOR_MAP_DATA_TYPE_FLOAT16, 2, p, gd, gs, bx, es,
      CU_TENSOR_MAP_INTERLEAVE_NONE, CU_TENSOR_MAP_SWIZZLE_128B,
      CU_TENSOR_MAP_L2_PROMOTION_L2_128B, CU_TENSOR_MAP_FLOAT_OOB_FILL_NONE);
}

extern "C" void kernel_launch(void* const* d_in, const int* in_sizes, int n_in,
                              void* d_out, int out_size) {
    static EncodeFn enc = nullptr;
    static void* xhp = nullptr;
    if (!enc) {
        cudaFuncSetAttribute(gemm_conv_kernel,
                             cudaFuncAttributeMaxDynamicSharedMemorySize, SMEM_DYN);
        void* fn = nullptr;
        cudaDriverEntryPointQueryResult qst;
        cudaGetDriverEntryPointByVersion("cuTensorMapEncodeTiled", &fn, 12000,
                                         cudaEnableDefault, &qst);
        enc = (EncodeFn)fn;
        cudaGetSymbolAddress(&xhp, g_xh);
    }
    CUtensorMap xm1, xm2;
    encXH(enc, &xm1, xhp);
    encXH(enc, &xm2, (char*)xhp + (size_t)ROWS_TOT * XKP * 2);

    prep_kernel<<<160, 1024>>>((const float*)d_in[2], (const float*)d_in[6]);
    xconv_kernel<<<dim3(7600, 2), 1024>>>((const float*)d_in[0], (const float*)d_in[1]);
    nop_kernel<<<1, 32>>>();
    gemm_conv_kernel<<<dim3(4, NCTA), NTHR, SMEM_DYN>>>(
        xm1, xm2, (const float*)d_in[3], (const float*)d_in[7]);
    finish_kernel<<<BSZ / 8, 256>>>((const float*)d_in[4], (const float*)d_in[5],
                                    (const float*)d_in[8], (const float*)d_in[9],
                                    (float*)d_out);
}

// round 13
// speedup vs baseline: 1.0857x; 1.0857x over previous
#include <cuda_runtime.h>
#include <cuda.h>
#include <cuda_fp16.h>
#include <cstdint>

#define BSZ   1024
#define LSEQ  200
#define CCH   80
#define OOUT  30
#define ROWS_TOT (BSZ * LSEQ)      // 204800
#define NCOL  240
#define KDIM  300
#define KSTR  320                  // zero-padded K for fp16 W in gmem
#define XKP   304                  // zero-padded K for fp16 X in gmem
#define BN    120                  // N per CTA (2 CTAs cover 240)
#define NCHUNK 5                   // K chunks of 64h (last: 3 of 4 k16 steps)
#define NCTA  1626
#define NTHR  384                  // 12 warps: 4M x 3N, warp tile 32x40
#define ASTG  16384                // A: 128 rows x 64h (128B rows, SW128)
#define BSTG  15360                // B: 120 rows x 64h (128B rows, SW128)
#define STG   (ASTG + BSTG)        // 31744
#define SMEM_DYN (3 * STG + 1024)  // 96256 -> 2 CTAs/SM
#define DSS   121

__device__ int    g_h[2][BSZ * CCH];
__device__ __half g_wh[2][NCOL * KSTR];
__device__ __half g_xh[2][ROWS_TOT * XKP];

// ---------------- PTX helpers ----------------
__device__ __forceinline__ uint32_t smem_u32(const void* p) {
    uint32_t a;
    asm("{ .reg .u64 t; cvta.to.shared.u64 t, %1; cvt.u32.u64 %0, t; }" : "=r"(a) : "l"(p));
    return a;
}
#define MBAR_INIT(a, c) asm volatile("mbarrier.init.shared.b64 [%0], %1;" :: "r"(a), "r"(c) : "memory")
#define MBAR_EXPECT(a, b) asm volatile("mbarrier.arrive.expect_tx.shared.b64 _, [%0], %1;" :: "r"(a), "r"(b) : "memory")
#define MBAR_WAIT(a, ph) do { \
    uint32_t _m = (a), _p = (ph), _d; \
    asm volatile("{\n\t.reg .pred p;\n\t" \
        "mbarrier.try_wait.parity.acquire.cta.shared::cta.b64 p, [%1], %2;\n\t" \
        "selp.b32 %0, 1, 0, p;\n\t}" : "=r"(_d) : "r"(_m), "r"(_p) : "memory"); \
    if (!_d) { \
        asm volatile("{\n\t.reg .pred P1;\n\tWL_%=:\n\t" \
            "mbarrier.try_wait.parity.acquire.cta.shared::cta.b64 P1, [%0], %1, 0x989680;\n\t" \
            "@P1 bra.uni WD_%=;\n\tbra.uni WL_%=;\n\tWD_%=:\n\t}" \
            :: "r"(_m), "r"(_p) : "memory"); \
    } } while (0)

__device__ __forceinline__ void tma2d(uint32_t dst, const CUtensorMap* m, int x, int y, uint32_t mb) {
    asm volatile("cp.async.bulk.tensor.2d.shared::cta.global.tile.mbarrier::complete_tx::bytes "
                 "[%0], [%1, {%2, %3}], [%4];" :: "r"(dst), "l"(m), "r"(x), "r"(y), "r"(mb) : "memory");
}
__device__ __forceinline__ uint32_t packh2(float lo, float hi) {
    uint32_t r;
    asm("cvt.rn.f16x2.f32 %0, %1, %2;" : "=r"(r) : "f"(hi), "f"(lo));
    return r;
}
__device__ __forceinline__ void ldsm4(uint32_t* r, uint32_t addr) {
    asm volatile("ldmatrix.sync.aligned.m8n8.x4.shared.b16 {%0,%1,%2,%3}, [%4];"
                 : "=r"(r[0]), "=r"(r[1]), "=r"(r[2]), "=r"(r[3]) : "r"(addr));
}
__device__ __forceinline__ void ldsm2(uint32_t* r, uint32_t addr) {
    asm volatile("ldmatrix.sync.aligned.m8n8.x2.shared.b16 {%0,%1}, [%2];"
                 : "=r"(r[0]), "=r"(r[1]) : "r"(addr));
}
__device__ __forceinline__ void mma16h(uint32_t* c, const uint32_t* a, uint32_t b0, uint32_t b1) {
    asm volatile("mma.sync.aligned.m16n8k16.row.col.f16.f16.f16.f16 "
                 "{%0,%1}, {%2,%3,%4,%5}, {%6,%7}, {%0,%1};"
                 : "+r"(c[0]), "+r"(c[1])
                 : "r"(a[0]), "r"(a[1]), "r"(a[2]), "r"(a[3]), "r"(b0), "r"(b1));
}

// ---------------- kernels ----------------
__global__ void nop_kernel() {}

__global__ void prep_kernel(const float* __restrict__ w1, const float* __restrict__ w2) {
    const int i = blockIdx.x * blockDim.x + threadIdx.x;   // 163840
    ((int*)g_h)[i] = 0;
    if (i < NCOL * KSTR) {
        const int row = i / KSTR, col = i % KSTR;
        g_wh[0][i] = __float2half_rn((col < KDIM) ? w1[row * KDIM + col] : 0.f);
        g_wh[1][i] = __float2half_rn((col < KDIM) ? w2[row * KDIM + col] : 0.f);
    }
}

// X fp32 -> fp16 gmem; one thread = one 8-half unit (38 units/row)
__global__ void __launch_bounds__(1024) xconv_kernel(
    const float* __restrict__ x1, const float* __restrict__ x2)
{
    const int g = blockIdx.x * 1024 + threadIdx.x;
    const int sub = blockIdx.y;
    const int row = g / 38, u = g - row * 38;
    const int k = u * 8;
    const float* src = (sub ? x2 : x1) + (long)row * KDIM + k;
    const float4 a = *(const float4*)src;
    float4 b = make_float4(0.f, 0.f, 0.f, 0.f);
    if (u < 37) b = *(const float4*)(src + 4);
    uint4 o;
    o.x = packh2(a.x, a.y); o.y = packh2(a.z, a.w);
    o.z = packh2(b.x, b.y); o.w = packh2(b.z, b.w);
    *(uint4*)(g_xh[sub] + (long)row * XKP + k) = o;
}

__global__ void __launch_bounds__(NTHR, 2) gemm_conv_kernel(
    const __grid_constant__ CUtensorMap xm1, const __grid_constant__ CUtensorMap xm2,
    const __grid_constant__ CUtensorMap wm1, const __grid_constant__ CUtensorMap wm2,
    const float* __restrict__ b1, const float* __restrict__ b2)
{
    extern __shared__ char dynsm[];
    __shared__ __align__(8) unsigned long long mb_full[3];

    const int tid = threadIdx.x, wid = tid >> 5, lane = tid & 31;
    const int warp_m = wid & 3, warp_n = wid >> 2;   // 4M x 3N, warp tile 32x40
    const int nsplit = blockIdx.x & 1;
    const int sub = blockIdx.x >> 1;
    const int nbase = nsplit * BN;
    const float* bc = sub ? b2 : b1;
    const CUtensorMap* xm = sub ? &xm2 : &xm1;
    const CUtensorMap* wm = sub ? &wm2 : &wm1;
    const int r0 = blockIdx.y * 126;

    const uint32_t raw = smem_u32(dynsm);
    const uint32_t sb = (raw + 1023u) & ~1023u;
    char* dptr = dynsm + (sb - raw);

    if (tid == 0) {
        MBAR_INIT(smem_u32(&mb_full[0]), 1);
        MBAR_INIT(smem_u32(&mb_full[1]), 1);
        MBAR_INIT(smem_u32(&mb_full[2]), 1);
        asm volatile("fence.proxy.async.shared::cta;" ::: "memory");
        #pragma unroll
        for (int c = 0; c < 3; c++) {
            const uint32_t mb = smem_u32(&mb_full[c]);
            MBAR_EXPECT(mb, STG);
            tma2d(sb + c * STG,        xm, c * 64, r0,    mb);
            tma2d(sb + c * STG + ASTG, wm, c * 64, nbase, mb);
        }
    }
    __syncthreads();                                 // mbar init visible to all

    uint32_t acc[2][5][2];
    #pragma unroll
    for (int mt = 0; mt < 2; mt++)
        #pragma unroll
        for (int nt = 0; nt < 5; nt++) { acc[mt][nt][0] = 0u; acc[mt][nt][1] = 0u; }

    // fragment lane addressing
    const int l15 = lane & 15, lhi = lane >> 4;
    const int arow0 = warp_m * 32 + l15;             // mt adds 16
    const int bmat = lane >> 3;
    const int brow_off4 = ((bmat & 2) << 2) + (lane & 7);
    const int bk_off4 = (bmat & 1) << 3;             // halves
    const int brow_off2 = lane & 7;
    const int bk_off2 = (bmat & 1) << 3;

    for (int c = 0; c < NCHUNK; c++) {
        const int s = c % 3;
        MBAR_WAIT(smem_u32(&mb_full[s]), (c / 3) & 1);
        const uint32_t Ab = sb + s * STG;
        const uint32_t Bb = Ab + ASTG;
        const int ksmax = (c == NCHUNK - 1) ? 3 : 4; // K=304 real
        #pragma unroll
        for (int ks = 0; ks < 4; ks++) {
            if (ks >= ksmax) break;
            uint32_t a[2][4];
            #pragma unroll
            for (int mt = 0; mt < 2; mt++) {
                const int arow = arow0 + mt * 16;
                ldsm4(a[mt], Ab + arow * 128 + ((ks * 32 + lhi * 16) ^ ((arow & 7) << 4)));
            }
            const uint32_t kb = ks * 32;             // bytes within chunk
            #pragma unroll
            for (int pair = 0; pair < 2; pair++) {
                const int brow = warp_n * 40 + pair * 16 + brow_off4;
                uint32_t b[4];
                ldsm4(b, Bb + brow * 128 + ((kb + bk_off4 * 2) ^ ((brow & 7) << 4)));
                mma16h(acc[0][2 * pair],     a[0], b[0], b[1]);
                mma16h(acc[1][2 * pair],     a[1], b[0], b[1]);
                mma16h(acc[0][2 * pair + 1], a[0], b[2], b[3]);
                mma16h(acc[1][2 * pair + 1], a[1], b[2], b[3]);
            }
            {
                const int brow = warp_n * 40 + 32 + brow_off2;
                uint32_t b[2];
                ldsm2(b, Bb + brow * 128 + ((kb + bk_off2 * 2) ^ ((brow & 7) << 4)));
                mma16h(acc[0][4], a[0], b[0], b[1]);
                mma16h(acc[1][4], a[1], b[0], b[1]);
            }
        }
        __syncthreads();                             // all warps done with stage s
        if (tid == 0 && c + 3 < NCHUNK) {
            const uint32_t mb = smem_u32(&mb_full[s]);
            MBAR_EXPECT(mb, STG);
            tma2d(sb + s * STG,        xm, (c + 3) * 64, r0,    mb);
            tma2d(sb + s * STG + ASTG, wm, (c + 3) * 64, nbase, mb);
        }
    }

    // ---- stage D (128 x 120) into smem ----
    const int grp = lane >> 2, tig = lane & 3;
    float* ds = (float*)dptr;
    #pragma unroll
    for (int mt = 0; mt < 2; mt++)
        #pragma unroll
        for (int nt = 0; nt < 5; nt++) {
            const int rb = warp_m * 32 + mt * 16 + grp;
            const int n0 = warp_n * 40 + nt * 8 + tig * 2;
            const float2 lo = __half22float2(*(__half2*)&acc[mt][nt][0]);
            const float2 hi = __half22float2(*(__half2*)&acc[mt][nt][1]);
            ds[rb * DSS + n0]           = lo.x;
            ds[rb * DSS + n0 + 1]       = lo.y;
            ds[(rb + 8) * DSS + n0]     = hi.x;
            ds[(rb + 8) * DSS + n0 + 1] = hi.y;
        }
    __syncthreads();

    // ---- 3-tap diagonal combine + bias + relu + segment max + atomicMax ----
    const int bA = r0 / LSEQ;
    const int chbase = nsplit * 40;
    for (int cl = wid; cl < 40; cl += 12) {
        const int ch = chbase + cl;
        const float bias = __ldg(&bc[ch]);
        float mA = 0.f, mB = 0.f;
        #pragma unroll
        for (int k = 0; k < 4; k++) {
            const int i = lane + 32 * k;
            if (i >= 126) continue;
            const int g = r0 + i;
            if (g + 2 >= ROWS_TOT) continue;
            if ((g % LSEQ) > (LSEQ - 3)) continue;
            float v = ds[i * DSS + 3 * cl] + ds[(i + 1) * DSS + 3 * cl + 1]
                    + ds[(i + 2) * DSS + 3 * cl + 2] + bias;
            v = fmaxf(v, 0.f);
            if (g / LSEQ == bA) mA = fmaxf(mA, v); else mB = fmaxf(mB, v);
        }
        #pragma unroll
        for (int off = 16; off; off >>= 1) {
            mA = fmaxf(mA, __shfl_xor_sync(0xffffffffu, mA, off));
            mB = fmaxf(mB, __shfl_xor_sync(0xffffffffu, mB, off));
        }
        if (lane == 0) {
            if (mA > 0.f) atomicMax(&g_h[sub][bA * CCH + ch], __float_as_int(mA));
            if (mB > 0.f && bA + 1 < BSZ)
                atomicMax(&g_h[sub][(bA + 1) * CCH + ch], __float_as_int(mB));
        }
    }
}

__global__ void __launch_bounds__(256) finish_kernel(
    const float* __restrict__ wfc1, const float* __restrict__ bfc1,
    const float* __restrict__ wfc2, const float* __restrict__ bfc2,
    float* __restrict__ out)
{
    const int wid = threadIdx.x >> 5, j = threadIdx.x & 31;
    const int b = blockIdx.x * 8 + wid;
    float p = 0.f;
    if (j < OOUT) {
        float s1 = bfc1[j], s2 = bfc2[j];
        const int* h1 = &g_h[0][b * CCH];
        const int* h2 = &g_h[1][b * CCH];
        #pragma unroll 8
        for (int c = 0; c < CCH; c++) {
            s1 += __int_as_float(h1[c]) * wfc1[j * CCH + c];
            s2 += __int_as_float(h2[c]) * wfc2[j * CCH + c];
        }
        p = fmaxf(s1, 0.f) * fmaxf(s2, 0.f);
    }
    #pragma unroll
    for (int off = 16; off; off >>= 1) p += __shfl_xor_sync(0xffffffffu, p, off);
    if (j == 0) out[b] = p;
}

// ---------------- host ----------------
typedef CUresult (*EncodeFn)(CUtensorMap*, CUtensorMapDataType, cuuint32_t, void*,
                             const cuuint64_t*, const cuuint64_t*, const cuuint32_t*, const cuuint32_t*,
                             CUtensorMapInterleave, CUtensorMapSwizzle, CUtensorMapL2promotion,
                             CUtensorMapFloatOOBfill);

static void encH(EncodeFn f, CUtensorMap* m, void* p, cuuint64_t d0, cuuint64_t d1,
                 cuuint32_t b1) {
    cuuint64_t gd[2] = {d0, d1};
    cuuint64_t gs[1] = {d0 * 2};
    cuuint32_t bx[2] = {64, b1};
    cuuint32_t es[2] = {1, 1};
    f(m, CU_TENSOR_MAP_DATA_TYPE_FLOAT16, 2, p, gd, gs, bx, es,
      CU_TENSOR_MAP_INTERLEAVE_NONE, CU_TENSOR_MAP_SWIZZLE_128B,
      CU_TENSOR_MAP_L2_PROMOTION_L2_128B, CU_TENSOR_MAP_FLOAT_OOB_FILL_NONE);
}

extern "C" void kernel_launch(void* const* d_in, const int* in_sizes, int n_in,
                              void* d_out, int out_size) {
    static EncodeFn enc = nullptr;
    static void* xhp = nullptr;
    static void* whp = nullptr;
    if (!enc) {
        cudaFuncSetAttribute(gemm_conv_kernel,
                             cudaFuncAttributeMaxDynamicSharedMemorySize, SMEM_DYN);
        void* fn = nullptr;
        cudaDriverEntryPointQueryResult qst;
        cudaGetDriverEntryPointByVersion("cuTensorMapEncodeTiled", &fn, 12000,
                                         cudaEnableDefault, &qst);
        enc = (EncodeFn)fn;
        cudaGetSymbolAddress(&xhp, g_xh);
        cudaGetSymbolAddress(&whp, g_wh);
    }
    CUtensorMap xm1, xm2, wm1, wm2;
    encH(enc, &xm1, xhp, XKP, ROWS_TOT, 128);
    encH(enc, &xm2, (char*)xhp + (size_t)ROWS_TOT * XKP * 2, XKP, ROWS_TOT, 128);
    encH(enc, &wm1, whp, KSTR, NCOL, BN);
    encH(enc, &wm2, (char*)whp + NCOL * KSTR * 2, KSTR, NCOL, BN);

    prep_kernel<<<160, 1024>>>((const float*)d_in[2], (const float*)d_in[6]);
    xconv_kernel<<<dim3(7600, 2), 1024>>>((const float*)d_in[0], (const float*)d_in[1]);
    nop_kernel<<<1, 32>>>();
    gemm_conv_kernel<<<dim3(4, NCTA), NTHR, SMEM_DYN>>>(
        xm1, xm2, wm1, wm2, (const float*)d_in[3], (const float*)d_in[7]);
    finish_kernel<<<BSZ / 8, 256>>>((const float*)d_in[4], (const float*)d_in[5],
                                    (const float*)d_in[8], (const float*)d_in[9],
                                    (float*)d_out);
}

// round 14
// speedup vs baseline: 1.1638x; 1.0719x over previous
#include <cuda_runtime.h>
#include <cuda.h>
#include <cuda_fp16.h>
#include <cstdint>

#define BSZ   1024
#define LSEQ  200
#define CCH   80
#define OOUT  30
#define ROWS_TOT (BSZ * LSEQ)      // 204800
#define NCOL  240
#define KDIM  300
#define KSTR  320                  // zero-padded K for fp16 W in gmem
#define XKP   304                  // zero-padded K for fp16 X in gmem
#define BN    120                  // N per CTA (2 CTAs cover 240)
#define NCHUNK 5                   // K chunks of 64h (last: 3 of 4 k16 steps)
#define NCTA  1626
#define NTHR  384                  // 12 warps: 4M x 3N, warp tile 32x40
#define ASTG  16384                // A: 128 rows x 64h (128B rows, SW128)
#define BSTG  15360                // B: 120 rows x 64h (128B rows, SW128)
#define STG   (ASTG + BSTG)        // 31744
#define SMEM_DYN (3 * STG + 1024)  // 96256 -> 2 CTAs/SM
#define DSS2  122                  // D staging stride in halves (61 words, odd)

__device__ int    g_h[2][BSZ * CCH];
__device__ __half g_wh[2][NCOL * KSTR];
__device__ __half g_xh[2][ROWS_TOT * XKP];

// ---------------- PTX helpers ----------------
__device__ __forceinline__ uint32_t smem_u32(const void* p) {
    uint32_t a;
    asm("{ .reg .u64 t; cvta.to.shared.u64 t, %1; cvt.u32.u64 %0, t; }" : "=r"(a) : "l"(p));
    return a;
}
#define MBAR_INIT(a, c) asm volatile("mbarrier.init.shared.b64 [%0], %1;" :: "r"(a), "r"(c) : "memory")
#define MBAR_EXPECT(a, b) asm volatile("mbarrier.arrive.expect_tx.shared.b64 _, [%0], %1;" :: "r"(a), "r"(b) : "memory")
#define MBAR_WAIT(a, ph) do { \
    uint32_t _m = (a), _p = (ph), _d; \
    asm volatile("{\n\t.reg .pred p;\n\t" \
        "mbarrier.try_wait.parity.acquire.cta.shared::cta.b64 p, [%1], %2;\n\t" \
        "selp.b32 %0, 1, 0, p;\n\t}" : "=r"(_d) : "r"(_m), "r"(_p) : "memory"); \
    if (!_d) { \
        asm volatile("{\n\t.reg .pred P1;\n\tWL_%=:\n\t" \
            "mbarrier.try_wait.parity.acquire.cta.shared::cta.b64 P1, [%0], %1, 0x989680;\n\t" \
            "@P1 bra.uni WD_%=;\n\tbra.uni WL_%=;\n\tWD_%=:\n\t}" \
            :: "r"(_m), "r"(_p) : "memory"); \
    } } while (0)

__device__ __forceinline__ void tma2d(uint32_t dst, const CUtensorMap* m, int x, int y, uint32_t mb) {
    asm volatile("cp.async.bulk.tensor.2d.shared::cta.global.tile.mbarrier::complete_tx::bytes "
                 "[%0], [%1, {%2, %3}], [%4];" :: "r"(dst), "l"(m), "r"(x), "r"(y), "r"(mb) : "memory");
}
__device__ __forceinline__ uint32_t packh2(float lo, float hi) {
    uint32_t r;
    asm("cvt.rn.f16x2.f32 %0, %1, %2;" : "=r"(r) : "f"(hi), "f"(lo));
    return r;
}
__device__ __forceinline__ void ldsm4(uint32_t* r, uint32_t addr) {
    asm volatile("ldmatrix.sync.aligned.m8n8.x4.shared.b16 {%0,%1,%2,%3}, [%4];"
                 : "=r"(r[0]), "=r"(r[1]), "=r"(r[2]), "=r"(r[3]) : "r"(addr));
}
__device__ __forceinline__ void ldsm2(uint32_t* r, uint32_t addr) {
    asm volatile("ldmatrix.sync.aligned.m8n8.x2.shared.b16 {%0,%1}, [%2];"
                 : "=r"(r[0]), "=r"(r[1]) : "r"(addr));
}
__device__ __forceinline__ void mma16h(uint32_t* c, const uint32_t* a, uint32_t b0, uint32_t b1) {
    asm volatile("mma.sync.aligned.m16n8k16.row.col.f16.f16.f16.f16 "
                 "{%0,%1}, {%2,%3,%4,%5}, {%6,%7}, {%0,%1};"
                 : "+r"(c[0]), "+r"(c[1])
                 : "r"(a[0]), "r"(a[1]), "r"(a[2]), "r"(a[3]), "r"(b0), "r"(b1));
}

// ---------------- kernels ----------------
__global__ void nop_kernel() {}

__global__ void prep_kernel(const float* __restrict__ w1, const float* __restrict__ w2) {
    const int i = blockIdx.x * blockDim.x + threadIdx.x;   // 163840
    ((int*)g_h)[i] = 0;
    if (i < NCOL * KSTR) {
        const int row = i / KSTR, col = i % KSTR;
        g_wh[0][i] = __float2half_rn((col < KDIM) ? w1[row * KDIM + col] : 0.f);
        g_wh[1][i] = __float2half_rn((col < KDIM) ? w2[row * KDIM + col] : 0.f);
    }
}

// X fp32 -> fp16 gmem; one thread = one 8-half unit (38 units/row)
__global__ void __launch_bounds__(1024) xconv_kernel(
    const float* __restrict__ x1, const float* __restrict__ x2)
{
    const int g = blockIdx.x * 1024 + threadIdx.x;
    const int sub = blockIdx.y;
    const int row = g / 38, u = g - row * 38;
    const int k = u * 8;
    const float* src = (sub ? x2 : x1) + (long)row * KDIM + k;
    const float4 a = *(const float4*)src;
    float4 b = make_float4(0.f, 0.f, 0.f, 0.f);
    if (u < 37) b = *(const float4*)(src + 4);
    uint4 o;
    o.x = packh2(a.x, a.y); o.y = packh2(a.z, a.w);
    o.z = packh2(b.x, b.y); o.w = packh2(b.z, b.w);
    *(uint4*)(g_xh[sub] + (long)row * XKP + k) = o;
}

__global__ void __launch_bounds__(NTHR, 2) gemm_conv_kernel(
    const __grid_constant__ CUtensorMap xm1, const __grid_constant__ CUtensorMap xm2,
    const __grid_constant__ CUtensorMap wm1, const __grid_constant__ CUtensorMap wm2,
    const float* __restrict__ b1, const float* __restrict__ b2)
{
    extern __shared__ char dynsm[];
    __shared__ __align__(8) unsigned long long mb_full[3];

    const int tid = threadIdx.x, wid = tid >> 5, lane = tid & 31;
    const int warp_m = wid & 3, warp_n = wid >> 2;   // 4M x 3N, warp tile 32x40
    const int nsplit = blockIdx.x & 1;
    const int sub = blockIdx.x >> 1;
    const int nbase = nsplit * BN;
    const float* bc = sub ? b2 : b1;
    const CUtensorMap* xm = sub ? &xm2 : &xm1;
    const CUtensorMap* wm = sub ? &wm2 : &wm1;
    const int r0 = blockIdx.y * 126;

    const uint32_t raw = smem_u32(dynsm);
    const uint32_t sb = (raw + 1023u) & ~1023u;
    char* dptr = dynsm + (sb - raw);

    if (tid == 0) {
        MBAR_INIT(smem_u32(&mb_full[0]), 1);
        MBAR_INIT(smem_u32(&mb_full[1]), 1);
        MBAR_INIT(smem_u32(&mb_full[2]), 1);
        asm volatile("fence.proxy.async.shared::cta;" ::: "memory");
        #pragma unroll
        for (int c = 0; c < 3; c++) {
            const uint32_t mb = smem_u32(&mb_full[c]);
            MBAR_EXPECT(mb, STG);
            tma2d(sb + c * STG,        xm, c * 64, r0,    mb);
            tma2d(sb + c * STG + ASTG, wm, c * 64, nbase, mb);
        }
    }
    __syncthreads();                                 // mbar init visible to all

    uint32_t acc[2][5][2];
    #pragma unroll
    for (int mt = 0; mt < 2; mt++)
        #pragma unroll
        for (int nt = 0; nt < 5; nt++) { acc[mt][nt][0] = 0u; acc[mt][nt][1] = 0u; }

    // fragment lane addressing
    const int l15 = lane & 15, lhi = lane >> 4;
    const int arow0 = warp_m * 32 + l15;             // mt adds 16
    const int bmat = lane >> 3;
    const int brow_off4 = ((bmat & 2) << 2) + (lane & 7);
    const int bk_off4 = (bmat & 1) << 3;             // halves
    const int brow_off2 = lane & 7;
    const int bk_off2 = (bmat & 1) << 3;

    for (int c = 0; c < NCHUNK; c++) {
        const int s = c % 3;
        MBAR_WAIT(smem_u32(&mb_full[s]), (c / 3) & 1);
        const uint32_t Ab = sb + s * STG;
        const uint32_t Bb = Ab + ASTG;
        const int ksmax = (c == NCHUNK - 1) ? 3 : 4; // K=304 real
        #pragma unroll
        for (int ks = 0; ks < 4; ks++) {
            if (ks >= ksmax) break;
            uint32_t a[2][4];
            #pragma unroll
            for (int mt = 0; mt < 2; mt++) {
                const int arow = arow0 + mt * 16;
                ldsm4(a[mt], Ab + arow * 128 + ((ks * 32 + lhi * 16) ^ ((arow & 7) << 4)));
            }
            const uint32_t kb = ks * 32;             // bytes within chunk
            #pragma unroll
            for (int pair = 0; pair < 2; pair++) {
                const int brow = warp_n * 40 + pair * 16 + brow_off4;
                uint32_t b[4];
                ldsm4(b, Bb + brow * 128 + ((kb + bk_off4 * 2) ^ ((brow & 7) << 4)));
                mma16h(acc[0][2 * pair],     a[0], b[0], b[1]);
                mma16h(acc[1][2 * pair],     a[1], b[0], b[1]);
                mma16h(acc[0][2 * pair + 1], a[0], b[2], b[3]);
                mma16h(acc[1][2 * pair + 1], a[1], b[2], b[3]);
            }
            {
                const int brow = warp_n * 40 + 32 + brow_off2;
                uint32_t b[2];
                ldsm2(b, Bb + brow * 128 + ((kb + bk_off2 * 2) ^ ((brow & 7) << 4)));
                mma16h(acc[0][4], a[0], b[0], b[1]);
                mma16h(acc[1][4], a[1], b[0], b[1]);
            }
        }
        // only chunks 0,1 trigger a reissue; later chunks run unsynchronized
        if (c + 3 < NCHUNK) {
            __syncthreads();                         // stage s fully consumed
            if (tid == 0) {
                const uint32_t mb = smem_u32(&mb_full[s]);
                MBAR_EXPECT(mb, STG);
                tma2d(sb + s * STG,        xm, (c + 3) * 64, r0,    mb);
                tma2d(sb + s * STG + ASTG, wm, (c + 3) * 64, nbase, mb);
            }
        }
    }
    __syncthreads();                                 // all reads done before ds reuse

    // ---- stage D (128 x 120) into smem as fp16 (acc is already fp16) ----
    const int grp = lane >> 2, tig = lane & 3;
    __half* ds = (__half*)dptr;
    #pragma unroll
    for (int mt = 0; mt < 2; mt++)
        #pragma unroll
        for (int nt = 0; nt < 5; nt++) {
            const int rb = warp_m * 32 + mt * 16 + grp;
            const int n0 = warp_n * 40 + nt * 8 + tig * 2;
            *(uint32_t*)&ds[rb * DSS2 + n0]       = acc[mt][nt][0];
            *(uint32_t*)&ds[(rb + 8) * DSS2 + n0] = acc[mt][nt][1];
        }
    __syncthreads();

    // ---- 3-tap diagonal combine + bias + relu + segment max + atomicMax ----
    const int bA = r0 / LSEQ;
    const int chbase = nsplit * 40;
    for (int cl = wid; cl < 40; cl += 12) {
        const int ch = chbase + cl;
        const float bias = __ldg(&bc[ch]);
        float mA = 0.f, mB = 0.f;
        #pragma unroll
        for (int k = 0; k < 4; k++) {
            const int i = lane + 32 * k;
            if (i >= 126) continue;
            const int g = r0 + i;
            if (g + 2 >= ROWS_TOT) continue;
            if ((g % LSEQ) > (LSEQ - 3)) continue;
            float v = __half2float(ds[i * DSS2 + 3 * cl])
                    + __half2float(ds[(i + 1) * DSS2 + 3 * cl + 1])
                    + __half2float(ds[(i + 2) * DSS2 + 3 * cl + 2]) + bias;
            v = fmaxf(v, 0.f);
            if (g / LSEQ == bA) mA = fmaxf(mA, v); else mB = fmaxf(mB, v);
        }
        #pragma unroll
        for (int off = 16; off; off >>= 1) {
            mA = fmaxf(mA, __shfl_xor_sync(0xffffffffu, mA, off));
            mB = fmaxf(mB, __shfl_xor_sync(0xffffffffu, mB, off));
        }
        if (lane == 0) {
            if (mA > 0.f) atomicMax(&g_h[sub][bA * CCH + ch], __float_as_int(mA));
            if (mB > 0.f && bA + 1 < BSZ)
                atomicMax(&g_h[sub][(bA + 1) * CCH + ch], __float_as_int(mB));
        }
    }
}

__global__ void __launch_bounds__(256) finish_kernel(
    const float* __restrict__ wfc1, const float* __restrict__ bfc1,
    const float* __restrict__ wfc2, const float* __restrict__ bfc2,
    float* __restrict__ out)
{
    const int wid = threadIdx.x >> 5, j = threadIdx.x & 31;
    const int b = blockIdx.x * 8 + wid;
    float p = 0.f;
    if (j < OOUT) {
        float s1 = bfc1[j], s2 = bfc2[j];
        const int* h1 = &g_h[0][b * CCH];
        const int* h2 = &g_h[1][b * CCH];
        #pragma unroll 8
        for (int c = 0; c < CCH; c++) {
            s1 += __int_as_float(h1[c]) * wfc1[j * CCH + c];
            s2 += __int_as_float(h2[c]) * wfc2[j * CCH + c];
        }
        p = fmaxf(s1, 0.f) * fmaxf(s2, 0.f);
    }
    #pragma unroll
    for (int off = 16; off; off >>= 1) p += __shfl_xor_sync(0xffffffffu, p, off);
    if (j == 0) out[b] = p;
}

// ---------------- host ----------------
typedef CUresult (*EncodeFn)(CUtensorMap*, CUtensorMapDataType, cuuint32_t, void*,
                             const cuuint64_t*, const cuuint64_t*, const cuuint32_t*, const cuuint32_t*,
                             CUtensorMapInterleave, CUtensorMapSwizzle, CUtensorMapL2promotion,
                             CUtensorMapFloatOOBfill);

static void encH(EncodeFn f, CUtensorMap* m, void* p, cuuint64_t d0, cuuint64_t d1,
                 cuuint32_t b1) {
    cuuint64_t gd[2] = {d0, d1};
    cuuint64_t gs[1] = {d0 * 2};
    cuuint32_t bx[2] = {64, b1};
    cuuint32_t es[2] = {1, 1};
    f(m, CU_TENSOR_MAP_DATA_TYPE_FLOAT16, 2, p, gd, gs, bx, es,
      CU_TENSOR_MAP_INTERLEAVE_NONE, CU_TENSOR_MAP_SWIZZLE_128B,
      CU_TENSOR_MAP_L2_PROMOTION_L2_128B, CU_TENSOR_MAP_FLOAT_OOB_FILL_NONE);
}

extern "C" void kernel_launch(void* const* d_in, const int* in_sizes, int n_in,
                              void* d_out, int out_size) {
    static EncodeFn enc = nullptr;
    static void* xhp = nullptr;
    static void* whp = nullptr;
    if (!enc) {
        cudaFuncSetAttribute(gemm_conv_kernel,
                             cudaFuncAttributeMaxDynamicSharedMemorySize, SMEM_DYN);
        void* fn = nullptr;
        cudaDriverEntryPointQueryResult qst;
        cudaGetDriverEntryPointByVersion("cuTensorMapEncodeTiled", &fn, 12000,
                                         cudaEnableDefault, &qst);
        enc = (EncodeFn)fn;
        cudaGetSymbolAddress(&xhp, g_xh);
        cudaGetSymbolAddress(&whp, g_wh);
    }
    CUtensorMap xm1, xm2, wm1, wm2;
    encH(enc, &xm1, xhp, XKP, ROWS_TOT, 128);
    encH(enc, &xm2, (char*)xhp + (size_t)ROWS_TOT * XKP * 2, XKP, ROWS_TOT, 128);
    encH(enc, &wm1, whp, KSTR, NCOL, BN);
    encH(enc, &wm2, (char*)whp + NCOL * KSTR * 2, KSTR, NCOL, BN);

    prep_kernel<<<160, 1024>>>((const float*)d_in[2], (const float*)d_in[6]);
    xconv_kernel<<<dim3(7600, 2), 1024>>>((const float*)d_in[0], (const float*)d_in[1]);
    nop_kernel<<<1, 32>>>();
    gemm_conv_kernel<<<dim3(4, NCTA), NTHR, SMEM_DYN>>>(
        xm1, xm2, wm1, wm2, (const float*)d_in[3], (const float*)d_in[7]);
    finish_kernel<<<BSZ / 8, 256>>>((const float*)d_in[4], (const float*)d_in[5],
                                    (const float*)d_in[8], (const float*)d_in[9],
                                    (float*)d_out);
}

// round 15
// speedup vs baseline: 1.2540x; 1.0775x over previous
#include <cuda_runtime.h>
#include <cuda.h>
#include <cuda_fp16.h>
#include <cstdint>

#define BSZ   1024
#define LSEQ  200
#define CCH   80
#define OOUT  30
#define ROWS_TOT (BSZ * LSEQ)      // 204800
#define NCOL  240
#define KDIM  300
#define KSTR  320                  // zero-padded K for fp16 W in gmem
#define XKP   304                  // zero-padded K for fp16 X in gmem
#define NCHUNK 5                   // K chunks of 64h (last: 3 of 4 k16 steps)
#define NCTA  1626
#define NTHR  384                  // 12 warps: 4M x 3N, warp tile 32x80
#define ASTG  16384                // A: 128 rows x 64h (128B rows, SW128)
#define BSTG  30720                // B: 240 rows x 64h (128B rows, SW128)
#define STG   (ASTG + BSTG)        // 47104
#define SMEM_DYN (2 * STG + 1024)  // 95232 -> 2 CTAs/SM
#define DSS2  242                  // D staging stride in halves (121 words, odd)

__device__ int    g_h[2][BSZ * CCH];
__device__ __half g_wh[2][NCOL * KSTR];
__device__ __half g_xh[2][ROWS_TOT * XKP];

// ---------------- PTX helpers ----------------
__device__ __forceinline__ uint32_t smem_u32(const void* p) {
    uint32_t a;
    asm("{ .reg .u64 t; cvta.to.shared.u64 t, %1; cvt.u32.u64 %0, t; }" : "=r"(a) : "l"(p));
    return a;
}
#define MBAR_INIT(a, c) asm volatile("mbarrier.init.shared.b64 [%0], %1;" :: "r"(a), "r"(c) : "memory")
#define MBAR_EXPECT(a, b) asm volatile("mbarrier.arrive.expect_tx.shared.b64 _, [%0], %1;" :: "r"(a), "r"(b) : "memory")
#define MBAR_WAIT(a, ph) do { \
    uint32_t _m = (a), _p = (ph), _d; \
    asm volatile("{\n\t.reg .pred p;\n\t" \
        "mbarrier.try_wait.parity.acquire.cta.shared::cta.b64 p, [%1], %2;\n\t" \
        "selp.b32 %0, 1, 0, p;\n\t}" : "=r"(_d) : "r"(_m), "r"(_p) : "memory"); \
    if (!_d) { \
        asm volatile("{\n\t.reg .pred P1;\n\tWL_%=:\n\t" \
            "mbarrier.try_wait.parity.acquire.cta.shared::cta.b64 P1, [%0], %1, 0x989680;\n\t" \
            "@P1 bra.uni WD_%=;\n\tbra.uni WL_%=;\n\tWD_%=:\n\t}" \
            :: "r"(_m), "r"(_p) : "memory"); \
    } } while (0)

__device__ __forceinline__ void tma2d(uint32_t dst, const CUtensorMap* m, int x, int y, uint32_t mb) {
    asm volatile("cp.async.bulk.tensor.2d.shared::cta.global.tile.mbarrier::complete_tx::bytes "
                 "[%0], [%1, {%2, %3}], [%4];" :: "r"(dst), "l"(m), "r"(x), "r"(y), "r"(mb) : "memory");
}
__device__ __forceinline__ uint32_t packh2(float lo, float hi) {
    uint32_t r;
    asm("cvt.rn.f16x2.f32 %0, %1, %2;" : "=r"(r) : "f"(hi), "f"(lo));
    return r;
}
__device__ __forceinline__ void ldsm4(uint32_t* r, uint32_t addr) {
    asm volatile("ldmatrix.sync.aligned.m8n8.x4.shared.b16 {%0,%1,%2,%3}, [%4];"
                 : "=r"(r[0]), "=r"(r[1]), "=r"(r[2]), "=r"(r[3]) : "r"(addr));
}
__device__ __forceinline__ void mma16h(uint32_t* c, const uint32_t* a, uint32_t b0, uint32_t b1) {
    asm volatile("mma.sync.aligned.m16n8k16.row.col.f16.f16.f16.f16 "
                 "{%0,%1}, {%2,%3,%4,%5}, {%6,%7}, {%0,%1};"
                 : "+r"(c[0]), "+r"(c[1])
                 : "r"(a[0]), "r"(a[1]), "r"(a[2]), "r"(a[3]), "r"(b0), "r"(b1));
}

// ---------------- kernels ----------------
__global__ void nop_kernel() {}

__global__ void prep_kernel(const float* __restrict__ w1, const float* __restrict__ w2) {
    const int i = blockIdx.x * blockDim.x + threadIdx.x;   // 163840
    ((int*)g_h)[i] = 0;
    if (i < NCOL * KSTR) {
        const int row = i / KSTR, col = i % KSTR;
        g_wh[0][i] = __float2half_rn((col < KDIM) ? w1[row * KDIM + col] : 0.f);
        g_wh[1][i] = __float2half_rn((col < KDIM) ? w2[row * KDIM + col] : 0.f);
    }
}

// X fp32 -> fp16 gmem; one thread = one 8-half unit (38 units/row)
__global__ void __launch_bounds__(1024) xconv_kernel(
    const float* __restrict__ x1, const float* __restrict__ x2)
{
    const int g = blockIdx.x * 1024 + threadIdx.x;
    const int sub = blockIdx.y;
    const int row = g / 38, u = g - row * 38;
    const int k = u * 8;
    const float* src = (sub ? x2 : x1) + (long)row * KDIM + k;
    const float4 a = *(const float4*)src;
    float4 b = make_float4(0.f, 0.f, 0.f, 0.f);
    if (u < 37) b = *(const float4*)(src + 4);
    uint4 o;
    o.x = packh2(a.x, a.y); o.y = packh2(a.z, a.w);
    o.z = packh2(b.x, b.y); o.w = packh2(b.z, b.w);
    *(uint4*)(g_xh[sub] + (long)row * XKP + k) = o;
}

__global__ void __launch_bounds__(NTHR, 2) gemm_conv_kernel(
    const __grid_constant__ CUtensorMap xm1, const __grid_constant__ CUtensorMap xm2,
    const __grid_constant__ CUtensorMap wm1, const __grid_constant__ CUtensorMap wm2,
    const float* __restrict__ b1, const float* __restrict__ b2)
{
    extern __shared__ char dynsm[];
    __shared__ __align__(8) unsigned long long mb_full[2];

    const int tid = threadIdx.x, wid = tid >> 5, lane = tid & 31;
    const int warp_m = wid & 3, warp_n = wid >> 2;   // 4M x 3N, warp tile 32x80
    const int sub = blockIdx.x;
    const float* bc = sub ? b2 : b1;
    const CUtensorMap* xm = sub ? &xm2 : &xm1;
    const CUtensorMap* wm = sub ? &wm2 : &wm1;
    const int r0 = blockIdx.y * 126;

    const uint32_t raw = smem_u32(dynsm);
    const uint32_t sb = (raw + 1023u) & ~1023u;
    char* dptr = dynsm + (sb - raw);

    if (tid == 0) {
        MBAR_INIT(smem_u32(&mb_full[0]), 1);
        MBAR_INIT(smem_u32(&mb_full[1]), 1);
        asm volatile("fence.proxy.async.shared::cta;" ::: "memory");
        #pragma unroll
        for (int c = 0; c < 2; c++) {
            const uint32_t mb = smem_u32(&mb_full[c]);
            MBAR_EXPECT(mb, STG);
            tma2d(sb + c * STG,        xm, c * 64, r0, mb);
            tma2d(sb + c * STG + ASTG, wm, c * 64, 0,  mb);
        }
    }
    __syncthreads();                                 // mbar init visible to all

    uint32_t acc[2][10][2];
    #pragma unroll
    for (int mt = 0; mt < 2; mt++)
        #pragma unroll
        for (int nt = 0; nt < 10; nt++) { acc[mt][nt][0] = 0u; acc[mt][nt][1] = 0u; }

    // fragment lane addressing
    const int l15 = lane & 15, lhi = lane >> 4;
    const int arow0 = warp_m * 32 + l15;             // mt adds 16
    const int bmat = lane >> 3;
    const int brow_off = ((bmat & 2) << 2) + (lane & 7);
    const int bk_off = (bmat & 1) << 3;              // halves

    for (int c = 0; c < NCHUNK; c++) {
        const int s = c & 1;
        MBAR_WAIT(smem_u32(&mb_full[s]), (c >> 1) & 1);
        const uint32_t Ab = sb + s * STG;
        const uint32_t Bb = Ab + ASTG;
        const int ksmax = (c == NCHUNK - 1) ? 3 : 4; // K=304 real
        #pragma unroll
        for (int ks = 0; ks < 4; ks++) {
            if (ks >= ksmax) break;
            uint32_t a[2][4];
            #pragma unroll
            for (int mt = 0; mt < 2; mt++) {
                const int arow = arow0 + mt * 16;
                ldsm4(a[mt], Ab + arow * 128 + ((ks * 32 + lhi * 16) ^ ((arow & 7) << 4)));
            }
            const uint32_t kb = ks * 32;             // bytes within chunk
            #pragma unroll
            for (int pair = 0; pair < 5; pair++) {
                const int brow = warp_n * 80 + pair * 16 + brow_off;
                uint32_t b[4];
                ldsm4(b, Bb + brow * 128 + ((kb + bk_off * 2) ^ ((brow & 7) << 4)));
                mma16h(acc[0][2 * pair],     a[0], b[0], b[1]);
                mma16h(acc[1][2 * pair],     a[1], b[0], b[1]);
                mma16h(acc[0][2 * pair + 1], a[0], b[2], b[3]);
                mma16h(acc[1][2 * pair + 1], a[1], b[2], b[3]);
            }
        }
        if (c + 2 < NCHUNK) {
            __syncthreads();                         // stage s fully consumed
            if (tid == 0) {
                const uint32_t mb = smem_u32(&mb_full[s]);
                MBAR_EXPECT(mb, STG);
                tma2d(sb + s * STG,        xm, (c + 2) * 64, r0, mb);
                tma2d(sb + s * STG + ASTG, wm, (c + 2) * 64, 0,  mb);
            }
        }
    }
    __syncthreads();                                 // all reads done before ds reuse

    // ---- stage D (128 x 240) into smem as fp16 ----
    const int grp = lane >> 2, tig = lane & 3;
    __half* ds = (__half*)dptr;
    #pragma unroll
    for (int mt = 0; mt < 2; mt++)
        #pragma unroll
        for (int nt = 0; nt < 10; nt++) {
            const int rb = warp_m * 32 + mt * 16 + grp;
            const int n0 = warp_n * 80 + nt * 8 + tig * 2;
            *(uint32_t*)&ds[rb * DSS2 + n0]       = acc[mt][nt][0];
            *(uint32_t*)&ds[(rb + 8) * DSS2 + n0] = acc[mt][nt][1];
        }
    __syncthreads();

    // ---- 3-tap diagonal combine + bias + relu + segment max + atomicMax ----
    const int bA = r0 / LSEQ;
    for (int ch = wid; ch < CCH; ch += 12) {
        const float bias = __ldg(&bc[ch]);
        float mA = 0.f, mB = 0.f;
        #pragma unroll
        for (int k = 0; k < 4; k++) {
            const int i = lane + 32 * k;
            if (i >= 126) continue;
            const int g = r0 + i;
            if (g + 2 >= ROWS_TOT) continue;
            if ((g % LSEQ) > (LSEQ - 3)) continue;
            float v = __half2float(ds[i * DSS2 + 3 * ch])
                    + __half2float(ds[(i + 1) * DSS2 + 3 * ch + 1])
                    + __half2float(ds[(i + 2) * DSS2 + 3 * ch + 2]) + bias;
            v = fmaxf(v, 0.f);
            if (g / LSEQ == bA) mA = fmaxf(mA, v); else mB = fmaxf(mB, v);
        }
        #pragma unroll
        for (int off = 16; off; off >>= 1) {
            mA = fmaxf(mA, __shfl_xor_sync(0xffffffffu, mA, off));
            mB = fmaxf(mB, __shfl_xor_sync(0xffffffffu, mB, off));
        }
        if (lane == 0) {
            if (mA > 0.f) atomicMax(&g_h[sub][bA * CCH + ch], __float_as_int(mA));
            if (mB > 0.f && bA + 1 < BSZ)
                atomicMax(&g_h[sub][(bA + 1) * CCH + ch], __float_as_int(mB));
        }
    }
}

__global__ void __launch_bounds__(256) finish_kernel(
    const float* __restrict__ wfc1, const float* __restrict__ bfc1,
    const float* __restrict__ wfc2, const float* __restrict__ bfc2,
    float* __restrict__ out)
{
    const int wid = threadIdx.x >> 5, j = threadIdx.x & 31;
    const int b = blockIdx.x * 8 + wid;
    float p = 0.f;
    if (j < OOUT) {
        float s1 = bfc1[j], s2 = bfc2[j];
        const int* h1 = &g_h[0][b * CCH];
        const int* h2 = &g_h[1][b * CCH];
        #pragma unroll 8
        for (int c = 0; c < CCH; c++) {
            s1 += __int_as_float(h1[c]) * wfc1[j * CCH + c];
            s2 += __int_as_float(h2[c]) * wfc2[j * CCH + c];
        }
        p = fmaxf(s1, 0.f) * fmaxf(s2, 0.f);
    }
    #pragma unroll
    for (int off = 16; off; off >>= 1) p += __shfl_xor_sync(0xffffffffu, p, off);
    if (j == 0) out[b] = p;
}

// ---------------- host ----------------
typedef CUresult (*EncodeFn)(CUtensorMap*, CUtensorMapDataType, cuuint32_t, void*,
                             const cuuint64_t*, const cuuint64_t*, const cuuint32_t*, const cuuint32_t*,
                             CUtensorMapInterleave, CUtensorMapSwizzle, CUtensorMapL2promotion,
                             CUtensorMapFloatOOBfill);

static void encH(EncodeFn f, CUtensorMap* m, void* p, cuuint64_t d0, cuuint64_t d1,
                 cuuint32_t b1) {
    cuuint64_t gd[2] = {d0, d1};
    cuuint64_t gs[1] = {d0 * 2};
    cuuint32_t bx[2] = {64, b1};
    cuuint32_t es[2] = {1, 1};
    f(m, CU_TENSOR_MAP_DATA_TYPE_FLOAT16, 2, p, gd, gs, bx, es,
      CU_TENSOR_MAP_INTERLEAVE_NONE, CU_TENSOR_MAP_SWIZZLE_128B,
      CU_TENSOR_MAP_L2_PROMOTION_L2_128B, CU_TENSOR_MAP_FLOAT_OOB_FILL_NONE);
}

extern "C" void kernel_launch(void* const* d_in, const int* in_sizes, int n_in,
                              void* d_out, int out_size) {
    static EncodeFn enc = nullptr;
    static void* xhp = nullptr;
    static void* whp = nullptr;
    if (!enc) {
        cudaFuncSetAttribute(gemm_conv_kernel,
                             cudaFuncAttributeMaxDynamicSharedMemorySize, SMEM_DYN);
        void* fn = nullptr;
        cudaDriverEntryPointQueryResult qst;
        cudaGetDriverEntryPointByVersion("cuTensorMapEncodeTiled", &fn, 12000,
                                         cudaEnableDefault, &qst);
        enc = (EncodeFn)fn;
        cudaGetSymbolAddress(&xhp, g_xh);
        cudaGetSymbolAddress(&whp, g_wh);
    }
    CUtensorMap xm1, xm2, wm1, wm2;
    encH(enc, &xm1, xhp, XKP, ROWS_TOT, 128);
    encH(enc, &xm2, (char*)xhp + (size_t)ROWS_TOT * XKP * 2, XKP, ROWS_TOT, 128);
    encH(enc, &wm1, whp, KSTR, NCOL, NCOL);
    encH(enc, &wm2, (char*)whp + NCOL * KSTR * 2, KSTR, NCOL, NCOL);

    prep_kernel<<<160, 1024>>>((const float*)d_in[2], (const float*)d_in[6]);
    xconv_kernel<<<dim3(7600, 2), 1024>>>((const float*)d_in[0], (const float*)d_in[1]);
    nop_kernel<<<1, 32>>>();
    gemm_conv_kernel<<<dim3(2, NCTA), NTHR, SMEM_DYN>>>(
        xm1, xm2, wm1, wm2, (const float*)d_in[3], (const float*)d_in[7]);
    finish_kernel<<<BSZ / 8, 256>>>((const float*)d_in[4], (const float*)d_in[5],
                                    (const float*)d_in[8], (const float*)d_in[9],
                                    (float*)d_out);
}